// round 11
// baseline (speedup 1.0000x reference)
#include <cuda_runtime.h>
#include <cuda_fp16.h>
#include <math.h>
#include <stdint.h>

// Problem constants
#define BATCH 4
#define SEQ   4096
#define DMODEL 1024
#define NHEAD 16
#define EDIM  64
#define NBH   (BATCH*NHEAD)       // 64
#define CHUNK 64
#define NCHUNK (SEQ/CHUNK)        // 64
#define M_TOK (BATCH*SEQ)         // 16384
#define KDIM  1024

#define EPS_FEAT 1.0001f
#define EPS_DEN  1e-6f

// ---------------------------------------------------------------------------
// Scratch (device globals, no runtime allocation)
// ---------------------------------------------------------------------------
__device__ float g_q[(size_t)NBH*SEQ*EDIM];
__device__ float g_k[(size_t)NBH*SEQ*EDIM];
__device__ float g_v[(size_t)NBH*SEQ*EDIM];
__device__ float g_kv[(size_t)NBH*NCHUNK*EDIM*EDIM];
__device__ float g_ksum[(size_t)NBH*NCHUNK*EDIM];

// fp16 split operands (A: hi+lo, B: hi only)
__device__ __half g_xh[(size_t)M_TOK*KDIM];
__device__ __half g_xl[(size_t)M_TOK*KDIM];
__device__ __half g_ah[(size_t)M_TOK*KDIM];   // attn output hi
__device__ __half g_al[(size_t)M_TOK*KDIM];   // attn output lo
__device__ __half g_wq[(size_t)3*DMODEL*KDIM];   // (3072,1024) = W^T fp16
__device__ __half g_wo[(size_t)DMODEL*KDIM];     // (1024,1024) = W^T fp16

__device__ __forceinline__ float elu1(float x) {
    return x > 0.f ? x + EPS_FEAT : expm1f(x) + EPS_FEAT;
}

__device__ __forceinline__ uint32_t smem_u32(const void* p) {
    uint32_t a;
    asm("{ .reg .u64 t; cvta.to.shared.u64 t, %1; cvt.u32.u64 %0, t; }"
        : "=r"(a) : "l"(p));
    return a;
}

__device__ __forceinline__ void cp_async16(uint32_t s, const void* g) {
    asm volatile("cp.async.cg.shared.global [%0], [%1], 16;" :: "r"(s), "l"(g));
}
__device__ __forceinline__ void cp_commit() {
    asm volatile("cp.async.commit_group;");
}
template<int N>
__device__ __forceinline__ void cp_wait() {
    asm volatile("cp.async.wait_group %0;" :: "n"(N));
}

__device__ __forceinline__ void ldmx4(uint32_t* r, uint32_t addr) {
    asm volatile("ldmatrix.sync.aligned.m8n8.x4.shared.b16 {%0,%1,%2,%3}, [%4];"
                 : "=r"(r[0]), "=r"(r[1]), "=r"(r[2]), "=r"(r[3]) : "r"(addr));
}

__device__ __forceinline__ void mma16816(float* d, const uint32_t* a, const uint32_t* b) {
    asm volatile(
        "mma.sync.aligned.m16n8k16.row.col.f32.f16.f16.f32 "
        "{%0,%1,%2,%3}, {%4,%5,%6,%7}, {%8,%9}, {%0,%1,%2,%3};"
        : "+f"(d[0]), "+f"(d[1]), "+f"(d[2]), "+f"(d[3])
        : "r"(a[0]), "r"(a[1]), "r"(a[2]), "r"(a[3]), "r"(b[0]), "r"(b[1]));
}

// ---------------------------------------------------------------------------
// Split x: fp32 -> (hi, lo) fp16
// ---------------------------------------------------------------------------
__global__ __launch_bounds__(256) void split_x_kernel(const float* __restrict__ xin) {
    size_t i = (size_t)blockIdx.x * blockDim.x + threadIdx.x;   // float4 index
    float4 v = ((const float4*)xin)[i];
    __half h0 = __float2half(v.x), h1 = __float2half(v.y);
    __half h2 = __float2half(v.z), h3 = __float2half(v.w);
    __half l0 = __float2half(v.x - __half2float(h0));
    __half l1 = __float2half(v.y - __half2float(h1));
    __half l2 = __float2half(v.z - __half2float(h2));
    __half l3 = __float2half(v.w - __half2float(h3));
    __half2* ph = (__half2*)g_xh;
    __half2* pl = (__half2*)g_xl;
    ph[2*i]   = __half2(h0, h1);
    ph[2*i+1] = __half2(h2, h3);
    pl[2*i]   = __half2(l0, l1);
    pl[2*i+1] = __half2(l2, l3);
}

// ---------------------------------------------------------------------------
// Transpose: W (K x N) fp32 -> Wt (N x K) fp16
// ---------------------------------------------------------------------------
template<int WHICH>
__global__ __launch_bounds__(256) void transpose_kernel(const float* __restrict__ W) {
    const int N = (WHICH == 0) ? 3 * DMODEL : DMODEL;
    __half* Th = (WHICH == 0) ? g_wq : g_wo;
    __shared__ float tile[32][33];
    int bx = blockIdx.x * 32;   // n
    int by = blockIdx.y * 32;   // k
    int tx = threadIdx.x, ty = threadIdx.y;
#pragma unroll
    for (int i = 0; i < 32; i += 8)
        tile[ty + i][tx] = W[(size_t)(by + ty + i) * N + bx + tx];
    __syncthreads();
#pragma unroll
    for (int i = 0; i < 32; i += 8) {
        float v = tile[tx][ty + i];
        int n = bx + ty + i, k = by + tx;
        Th[(size_t)n * KDIM + k] = __float2half(v);
    }
}

// ---------------------------------------------------------------------------
// HMMA GEMM (fp16, 2-term split): C = A(M,1024) @ Bt(N,1024)^T + bias
// 128x128 CTA tile, 512 threads (16 warps 4x4, 32x32/warp), K-chunk 128
// (two K-64 subtiles per tile, preserving the 128B-row swizzle), 2-stage
// cp.async pipeline with load-after-sync ordering. Staged smem epilogue.
// MODE 0: -> q/k/v feature-map scatter ; MODE 1: -> C
// ---------------------------------------------------------------------------
#define STAGE_BYTES 98304                  // 3 tiles x 2 subtiles x 16 KB
#define GEMM_SMEM_BYTES (2 * STAGE_BYTES)  // 192 KB
#define NKCHUNK (KDIM / 128)               // 8
#define CPAD 132

template<int MODE>
__global__ __launch_bounds__(512) void mma_gemm_kernel(
    const float* __restrict__ bias, float* __restrict__ C, int N)
{
    extern __shared__ char smem[];
    const __half* Ah = (MODE == 0) ? g_xh : g_ah;
    const __half* Al = (MODE == 0) ? g_xl : g_al;
    const __half* Bm = (MODE == 0) ? g_wq : g_wo;

    const uint32_t sbase = smem_u32(smem);
    const int t = threadIdx.x;
    const int lane = t & 31, wid = t >> 5;
    const int wm = wid & 3, wn = wid >> 2;       // warp grid 4 x 4
    const int brow = blockIdx.y * 128;
    const int bcol = blockIdx.x * 128;

    float acc[2][4][4];
#pragma unroll
    for (int i = 0; i < 2; i++)
#pragma unroll
        for (int j = 0; j < 4; j++)
#pragma unroll
            for (int r = 0; r < 4; r++) acc[i][j][r] = 0.f;

    // Load K-chunk c (k0 = c*128) into stage st.
    // Layout: Ah sub0 @0, Ah sub1 @16K, Al @32K+, B @64K+ (sub stride 16K).
    auto ld_stage = [&](int st, int c) {
        int k0 = c * 128;
        const __half* srcs[3] = { Ah, Al, Bm };
#pragma unroll
        for (int u = 0; u < 12; u++) {
            int cid = u * 512 + t;               // 0..6143
            int t3 = cid >> 11;                  // 0..2
            int w = cid & 2047;
            int row = w >> 4;
            int kc16 = w & 15;
            int sub = kc16 >> 3, kc = kc16 & 7;
            int rowoff = (t3 < 2) ? brow : bcol;
            const void* g = srcs[t3] + (size_t)(rowoff + row) * KDIM
                          + k0 + sub * 64 + kc * 8;
            uint32_t d = sbase + st * STAGE_BYTES + t3 * 32768 + sub * 16384
                       + row * 128 + ((kc ^ (row & 7)) << 4);
            cp_async16(d, g);
        }
    };

    const int arl = lane & 15;
    const int ach = lane >> 4;
    const int brl = (lane & 7) + ((lane >> 4) << 3);
    const int bch = (lane >> 3) & 1;

    auto compute = [&](int st) {
        uint32_t tb = sbase + st * STAGE_BYTES;
        uint32_t ahf[2][2][4], alf[2][2][4], bf[2][4][2];
        auto ldfrag = [&](int u, int buf) {
            int sub = u >> 2;
            int kc0 = 2 * (u & 3);
            uint32_t sb16 = tb + sub * 16384;
#pragma unroll
            for (int i = 0; i < 2; i++) {
                int row = wm * 32 + i * 16 + arl;
                uint32_t off = row * 128 + (((kc0 + ach) ^ (row & 7)) << 4);
                ldmx4(ahf[buf][i], sb16 + off);
                ldmx4(alf[buf][i], sb16 + 32768 + off);
            }
#pragma unroll
            for (int jj = 0; jj < 2; jj++) {
                int row = wn * 32 + jj * 16 + brl;
                uint32_t off = row * 128 + (((kc0 + bch) ^ (row & 7)) << 4);
                uint32_t r[4];
                ldmx4(r, sb16 + 65536 + off);
                bf[buf][2*jj][0] = r[0]; bf[buf][2*jj][1] = r[1];
                bf[buf][2*jj+1][0] = r[2]; bf[buf][2*jj+1][1] = r[3];
            }
        };
        ldfrag(0, 0);
#pragma unroll
        for (int u = 0; u < 8; u++) {
            int cur = u & 1;
            if (u < 7) ldfrag(u + 1, cur ^ 1);
#pragma unroll
            for (int i = 0; i < 2; i++)
#pragma unroll
                for (int j = 0; j < 4; j++) {
                    mma16816(acc[i][j], ahf[cur][i], bf[cur][j]);
                    mma16816(acc[i][j], alf[cur][i], bf[cur][j]);
                }
        }
    };

    ld_stage(0, 0); cp_commit();
    ld_stage(1, 1); cp_commit();
#pragma unroll 1
    for (int c = 0; c < NKCHUNK; c++) {
        if (c == NKCHUNK - 1) cp_wait<0>(); else cp_wait<1>();
        __syncthreads();
        compute(c & 1);
        if (c < NKCHUNK - 2) {
            __syncthreads();                 // all warps done with stage c&1
            ld_stage(c & 1, c + 2);
            cp_commit();
        }
    }

    // ---- staged epilogue: regs -> smem -> coalesced global ----
    __syncthreads();
    float* cs = (float*)smem;             // 128 x CPAD floats
    const int gid = lane >> 2;
    const int tq  = lane & 3;
#pragma unroll
    for (int i = 0; i < 2; i++)
#pragma unroll
        for (int j = 0; j < 4; j++)
#pragma unroll
            for (int r = 0; r < 4; r++) {
                int m = wm * 32 + i * 16 + gid + ((r >> 1) << 3);
                int n = wn * 32 + j * 8 + 2 * tq + (r & 1);
                cs[m * CPAD + n] = acc[i][j][r] + bias[bcol + n];
            }
    __syncthreads();

    {
        int row = t & 127;                // local row
        int q4  = t >> 7;                 // 0..3, 32-float column chunk
        int m = brow + row;
        float vals[32];
#pragma unroll
        for (int u = 0; u < 8; u++)
            *(float4*)&vals[u * 4] = *(float4*)&cs[row * CPAD + q4 * 32 + u * 4];
        if (MODE == 0) {
            int b = m >> 12;
            int l = m & 4095;
            int ng = bcol + q4 * 32;
            int part = ng >> 10;
            int d = ng & 1023;
            int h = d >> 6, e0 = d & 63;
            size_t idx = (((size_t)(b * NHEAD + h)) * SEQ + l) * EDIM + e0;
            float* dst;
            if (part == 0) {
                dst = g_q;
#pragma unroll
                for (int u = 0; u < 32; u++) vals[u] = elu1(vals[u] * 0.125f);
            } else if (part == 1) {
                dst = g_k;
#pragma unroll
                for (int u = 0; u < 32; u++) vals[u] = elu1(vals[u]);
            } else {
                dst = g_v;
            }
#pragma unroll
            for (int u = 0; u < 8; u++)
                *(float4*)&dst[idx + u * 4] = *(float4*)&vals[u * 4];
        } else {
            float* dst = C + (size_t)m * N + bcol + q4 * 32;
#pragma unroll
            for (int u = 0; u < 8; u++)
                *(float4*)&dst[u * 4] = *(float4*)&vals[u * 4];
        }
    }
}

// ---------------------------------------------------------------------------
// Fused K2+K3: per-bh persistent block (512 threads); running KV/ksum prefix
// in registers. Writes the EXCLUSIVE prefix for each chunk.
// ---------------------------------------------------------------------------
__global__ __launch_bounds__(512) void state_scan_kernel() {
    int bh = blockIdx.x;
    __shared__ float Ks[CHUNK * EDIM];
    __shared__ float Vs[CHUNK * EDIM];
    int t = threadIdx.x;
    int e0 = (t >> 4) << 1;      // 2 e-rows per thread (32 groups x 2 = 64)
    int f0 = (t & 15) << 2;      // 4 f-cols

    float run[2][4];
#pragma unroll
    for (int i = 0; i < 2; i++)
#pragma unroll
        for (int x = 0; x < 4; x++) run[i][x] = 0.f;
    float runk = 0.f;

#pragma unroll 1
    for (int c = 0; c < NCHUNK; c++) {
        __syncthreads();
        size_t base = ((size_t)bh * SEQ + (size_t)c * CHUNK) * EDIM;
        for (int s = t; s < CHUNK * EDIM / 4; s += 512) {
            ((float4*)Ks)[s] = *(const float4*)(g_k + base + 4 * s);
            ((float4*)Vs)[s] = *(const float4*)(g_v + base + 4 * s);
        }
        __syncthreads();

        float* kvo = g_kv + ((size_t)bh * NCHUNK + c) * (EDIM * EDIM);
#pragma unroll
        for (int i = 0; i < 2; i++) {
            float4 o = make_float4(run[i][0], run[i][1], run[i][2], run[i][3]);
            *(float4*)&kvo[(e0 + i) * EDIM + f0] = o;
        }
        if (t < EDIM)
            g_ksum[((size_t)bh * NCHUNK + c) * EDIM + t] = runk;

#pragma unroll 4
        for (int j = 0; j < CHUNK; j++) {
            float2 kq = *(float2*)&Ks[j * EDIM + e0];
            float4 vq = *(float4*)&Vs[j * EDIM + f0];
            float kr[2] = {kq.x, kq.y};
            float vr[4] = {vq.x, vq.y, vq.z, vq.w};
#pragma unroll
            for (int i = 0; i < 2; i++)
#pragma unroll
                for (int x = 0; x < 4; x++)
                    run[i][x] = fmaf(kr[i], vr[x], run[i][x]);
        }
        if (t < EDIM) {
            float s = 0.f;
            for (int j = 0; j < CHUNK; j++) s += Ks[j * EDIM + t];
            runk += s;
        }
    }
}

// ---------------------------------------------------------------------------
// K4: per-(bh,chunk) output, 4x4 blocking + float4 loads.
// Writes fp16 hi/lo split directly (feeds the output-projection GEMM).
// ---------------------------------------------------------------------------
#define PAD 68
#define K4_SMEM_FLOATS (5 * 64 * PAD + 64 + 64)
__global__ __launch_bounds__(256) void attn_out_kernel() {
    extern __shared__ float sm[];
    float* Qs   = sm;                  // 64*68
    float* Ks   = Qs + 64 * PAD;
    float* Vs   = Ks + 64 * PAD;
    float* Ss   = Vs + 64 * PAD;
    float* KVs  = Ss + 64 * PAD;
    float* ksum = KVs + 64 * PAD;
    float* denr = ksum + 64;

    int bh = blockIdx.x;
    int c  = blockIdx.y;
    int t  = threadIdx.x;

    size_t base = ((size_t)bh * SEQ + (size_t)c * CHUNK) * EDIM;
    const float* kvp = g_kv + ((size_t)bh * NCHUNK + c) * (EDIM * EDIM);
    for (int s = t; s < CHUNK * EDIM; s += 256) {
        int i = s >> 6, e = s & 63;
        Qs[i * PAD + e] = g_q[base + s];
        Ks[i * PAD + e] = g_k[base + s];
        Vs[i * PAD + e] = g_v[base + s];
        KVs[i * PAD + e] = kvp[s];
    }
    if (t < EDIM) ksum[t] = g_ksum[((size_t)bh * NCHUNK + c) * EDIM + t];
    __syncthreads();

    // pass 1: S = Q K^T, store masked (zeros above diagonal)
    {
        int i0 = (t >> 4) << 2;
        int j0 = (t & 15) << 2;
        float a[4][4];
#pragma unroll
        for (int i = 0; i < 4; i++)
#pragma unroll
            for (int j = 0; j < 4; j++) a[i][j] = 0.f;
#pragma unroll 4
        for (int e = 0; e < EDIM; e += 4) {
            float4 q[4], k[4];
#pragma unroll
            for (int i = 0; i < 4; i++) q[i] = *(float4*)&Qs[(i0 + i) * PAD + e];
#pragma unroll
            for (int j = 0; j < 4; j++) k[j] = *(float4*)&Ks[(j0 + j) * PAD + e];
#pragma unroll
            for (int i = 0; i < 4; i++)
#pragma unroll
                for (int j = 0; j < 4; j++) {
                    a[i][j] = fmaf(q[i].x, k[j].x, a[i][j]);
                    a[i][j] = fmaf(q[i].y, k[j].y, a[i][j]);
                    a[i][j] = fmaf(q[i].z, k[j].z, a[i][j]);
                    a[i][j] = fmaf(q[i].w, k[j].w, a[i][j]);
                }
        }
#pragma unroll
        for (int i = 0; i < 4; i++) {
            float4 o;
            o.x = (j0 + 0 <= i0 + i) ? a[i][0] : 0.f;
            o.y = (j0 + 1 <= i0 + i) ? a[i][1] : 0.f;
            o.z = (j0 + 2 <= i0 + i) ? a[i][2] : 0.f;
            o.w = (j0 + 3 <= i0 + i) ? a[i][3] : 0.f;
            *(float4*)&Ss[(i0 + i) * PAD + j0] = o;
        }
    }
    __syncthreads();

    // denominators
    if (t < CHUNK) {
        int i = t;
        float dr = 0.f, d2 = 0.f;
        for (int j = 0; j < CHUNK; j++) dr += Ss[i * PAD + j];
        for (int e = 0; e < EDIM; e++) d2 = fmaf(Qs[i * PAD + e], ksum[e], d2);
        denr[i] = dr + d2 + EPS_DEN;
    }
    __syncthreads();

    // pass 2: out = (S V + Q KV) / den, write fp16 hi/lo
    {
        int i0 = (t >> 4) << 2;
        int e0 = (t & 15) << 2;
        float a[4][4];
#pragma unroll
        for (int i = 0; i < 4; i++)
#pragma unroll
            for (int x = 0; x < 4; x++) a[i][x] = 0.f;
#pragma unroll 4
        for (int j = 0; j < CHUNK; j += 4) {
            float4 srow[4], vrow[4];
#pragma unroll
            for (int i = 0; i < 4; i++) srow[i] = *(float4*)&Ss[(i0 + i) * PAD + j];
#pragma unroll
            for (int jj = 0; jj < 4; jj++) vrow[jj] = *(float4*)&Vs[(j + jj) * PAD + e0];
#pragma unroll
            for (int i = 0; i < 4; i++) {
                float sv[4] = {srow[i].x, srow[i].y, srow[i].z, srow[i].w};
#pragma unroll
                for (int jj = 0; jj < 4; jj++) {
                    a[i][0] = fmaf(sv[jj], vrow[jj].x, a[i][0]);
                    a[i][1] = fmaf(sv[jj], vrow[jj].y, a[i][1]);
                    a[i][2] = fmaf(sv[jj], vrow[jj].z, a[i][2]);
                    a[i][3] = fmaf(sv[jj], vrow[jj].w, a[i][3]);
                }
            }
        }
#pragma unroll 4
        for (int f = 0; f < EDIM; f += 4) {
            float4 qrow[4], kvr[4];
#pragma unroll
            for (int i = 0; i < 4; i++) qrow[i] = *(float4*)&Qs[(i0 + i) * PAD + f];
#pragma unroll
            for (int jj = 0; jj < 4; jj++) kvr[jj] = *(float4*)&KVs[(f + jj) * PAD + e0];
#pragma unroll
            for (int i = 0; i < 4; i++) {
                float qv[4] = {qrow[i].x, qrow[i].y, qrow[i].z, qrow[i].w};
#pragma unroll
                for (int jj = 0; jj < 4; jj++) {
                    a[i][0] = fmaf(qv[jj], kvr[jj].x, a[i][0]);
                    a[i][1] = fmaf(qv[jj], kvr[jj].y, a[i][1]);
                    a[i][2] = fmaf(qv[jj], kvr[jj].z, a[i][2]);
                    a[i][3] = fmaf(qv[jj], kvr[jj].w, a[i][3]);
                }
            }
        }

        int b = bh >> 4;
        int h = bh & 15;
#pragma unroll
        for (int i = 0; i < 4; i++) {
            int l = c * CHUNK + i0 + i;
            float inv = 1.f / denr[i0 + i];
            size_t idx = ((size_t)b * SEQ + l) * DMODEL + h * EDIM + e0;
            __half hv[4], lv[4];
#pragma unroll
            for (int x = 0; x < 4; x++) {
                float v = a[i][x] * inv;
                hv[x] = __float2half(v);
                lv[x] = __float2half(v - __half2float(hv[x]));
            }
            *(uint2*)(g_ah + idx) = *(uint2*)hv;
            *(uint2*)(g_al + idx) = *(uint2*)lv;
        }
    }
}

// ---------------------------------------------------------------------------
extern "C" void kernel_launch(void* const* d_in, const int* in_sizes, int n_in,
                              void* d_out, int out_size) {
    const float* x     = (const float*)d_in[0];
    const float* W_qkv = (const float*)d_in[1];
    const float* b_qkv = (const float*)d_in[2];
    const float* W_out = (const float*)d_in[3];
    const float* b_out = (const float*)d_in[4];
    float* out = (float*)d_out;

    static int attr_set = 0;
    if (!attr_set) {
        cudaFuncSetAttribute(mma_gemm_kernel<0>,
                             cudaFuncAttributeMaxDynamicSharedMemorySize, GEMM_SMEM_BYTES);
        cudaFuncSetAttribute(mma_gemm_kernel<1>,
                             cudaFuncAttributeMaxDynamicSharedMemorySize, GEMM_SMEM_BYTES);
        cudaFuncSetAttribute(attn_out_kernel,
                             cudaFuncAttributeMaxDynamicSharedMemorySize,
                             K4_SMEM_FLOATS * sizeof(float));
        attr_set = 1;
    }

    // prep
    split_x_kernel<<<(size_t)M_TOK * KDIM / 4 / 256, 256>>>(x);
    transpose_kernel<0><<<dim3(3 * DMODEL / 32, KDIM / 32), dim3(32, 8)>>>(W_qkv);
    transpose_kernel<1><<<dim3(DMODEL / 32, KDIM / 32), dim3(32, 8)>>>(W_out);

    // K1: qkv GEMM
    mma_gemm_kernel<0><<<dim3(3 * DMODEL / 128, M_TOK / 128), 512, GEMM_SMEM_BYTES>>>(
        b_qkv, nullptr, 3 * DMODEL);

    // attention
    state_scan_kernel<<<NBH, 512>>>();
    attn_out_kernel<<<dim3(NBH, NCHUNK), 256, K4_SMEM_FLOATS * sizeof(float)>>>();

    // output projection
    mma_gemm_kernel<1><<<dim3(DMODEL / 128, M_TOK / 128), 512, GEMM_SMEM_BYTES>>>(
        b_out, out, DMODEL);
}

// round 12
// speedup vs baseline: 1.0015x; 1.0015x over previous
#include <cuda_runtime.h>
#include <cuda_fp16.h>
#include <math.h>
#include <stdint.h>

// Problem constants
#define BATCH 4
#define SEQ   4096
#define DMODEL 1024
#define NHEAD 16
#define EDIM  64
#define NBH   (BATCH*NHEAD)       // 64
#define CHUNK 64
#define NCHUNK (SEQ/CHUNK)        // 64
#define M_TOK (BATCH*SEQ)         // 16384
#define KDIM  1024

#define EPS_FEAT 1.0001f
#define EPS_DEN  1e-6f

// ---------------------------------------------------------------------------
// Scratch (device globals, no runtime allocation)
// ---------------------------------------------------------------------------
__device__ float g_q[(size_t)NBH*SEQ*EDIM];
__device__ float g_k[(size_t)NBH*SEQ*EDIM];
__device__ float g_v[(size_t)NBH*SEQ*EDIM];
__device__ float g_kv[(size_t)NBH*NCHUNK*EDIM*EDIM];
__device__ float g_ksum[(size_t)NBH*NCHUNK*EDIM];

// fp16 split operands (A: hi+lo, B: hi only)
__device__ __half g_xh[(size_t)M_TOK*KDIM];
__device__ __half g_xl[(size_t)M_TOK*KDIM];
__device__ __half g_ah[(size_t)M_TOK*KDIM];   // attn output hi
__device__ __half g_al[(size_t)M_TOK*KDIM];   // attn output lo
__device__ __half g_wq[(size_t)3*DMODEL*KDIM];   // (3072,1024) = W^T fp16
__device__ __half g_wo[(size_t)DMODEL*KDIM];     // (1024,1024) = W^T fp16

__device__ __forceinline__ float elu1(float x) {
    return x > 0.f ? x + EPS_FEAT : expm1f(x) + EPS_FEAT;
}

__device__ __forceinline__ uint32_t smem_u32(const void* p) {
    uint32_t a;
    asm("{ .reg .u64 t; cvta.to.shared.u64 t, %1; cvt.u32.u64 %0, t; }"
        : "=r"(a) : "l"(p));
    return a;
}

__device__ __forceinline__ void cp_async16(uint32_t s, const void* g) {
    asm volatile("cp.async.cg.shared.global [%0], [%1], 16;" :: "r"(s), "l"(g));
}
__device__ __forceinline__ void cp_commit() {
    asm volatile("cp.async.commit_group;");
}
template<int N>
__device__ __forceinline__ void cp_wait() {
    asm volatile("cp.async.wait_group %0;" :: "n"(N));
}

__device__ __forceinline__ void ldmx4(uint32_t* r, uint32_t addr) {
    asm volatile("ldmatrix.sync.aligned.m8n8.x4.shared.b16 {%0,%1,%2,%3}, [%4];"
                 : "=r"(r[0]), "=r"(r[1]), "=r"(r[2]), "=r"(r[3]) : "r"(addr));
}

__device__ __forceinline__ void mma16816(float* d, const uint32_t* a, const uint32_t* b) {
    asm volatile(
        "mma.sync.aligned.m16n8k16.row.col.f32.f16.f16.f32 "
        "{%0,%1,%2,%3}, {%4,%5,%6,%7}, {%8,%9}, {%0,%1,%2,%3};"
        : "+f"(d[0]), "+f"(d[1]), "+f"(d[2]), "+f"(d[3])
        : "r"(a[0]), "r"(a[1]), "r"(a[2]), "r"(a[3]), "r"(b[0]), "r"(b[1]));
}

// ---------------------------------------------------------------------------
// Split x: fp32 -> (hi, lo) fp16
// ---------------------------------------------------------------------------
__global__ __launch_bounds__(256) void split_x_kernel(const float* __restrict__ xin) {
    size_t i = (size_t)blockIdx.x * blockDim.x + threadIdx.x;   // float4 index
    float4 v = ((const float4*)xin)[i];
    __half h0 = __float2half(v.x), h1 = __float2half(v.y);
    __half h2 = __float2half(v.z), h3 = __float2half(v.w);
    __half l0 = __float2half(v.x - __half2float(h0));
    __half l1 = __float2half(v.y - __half2float(h1));
    __half l2 = __float2half(v.z - __half2float(h2));
    __half l3 = __float2half(v.w - __half2float(h3));
    __half2* ph = (__half2*)g_xh;
    __half2* pl = (__half2*)g_xl;
    ph[2*i]   = __half2(h0, h1);
    ph[2*i+1] = __half2(h2, h3);
    pl[2*i]   = __half2(l0, l1);
    pl[2*i+1] = __half2(l2, l3);
}

// ---------------------------------------------------------------------------
// Transpose: W (K x N) fp32 -> Wt (N x K) fp16
// ---------------------------------------------------------------------------
template<int WHICH>
__global__ __launch_bounds__(256) void transpose_kernel(const float* __restrict__ W) {
    const int N = (WHICH == 0) ? 3 * DMODEL : DMODEL;
    __half* Th = (WHICH == 0) ? g_wq : g_wo;
    __shared__ float tile[32][33];
    int bx = blockIdx.x * 32;   // n
    int by = blockIdx.y * 32;   // k
    int tx = threadIdx.x, ty = threadIdx.y;
#pragma unroll
    for (int i = 0; i < 32; i += 8)
        tile[ty + i][tx] = W[(size_t)(by + ty + i) * N + bx + tx];
    __syncthreads();
#pragma unroll
    for (int i = 0; i < 32; i += 8) {
        float v = tile[tx][ty + i];
        int n = bx + ty + i, k = by + tx;
        Th[(size_t)n * KDIM + k] = __float2half(v);
    }
}

// ---------------------------------------------------------------------------
// HMMA GEMM (fp16, 2-term split): C = A(M,1024) @ Bt(N,1024)^T + bias
// 128x128 CTA tile, 512 threads (16 warps 4x4, 32x32/warp), K-chunk 128
// (two K-64 subtiles per tile, preserving the 128B-row swizzle), 2-stage
// cp.async pipeline with load-after-sync ordering. Staged smem epilogue.
// MODE 0: -> q/k/v feature-map scatter ; MODE 1: -> C
// ---------------------------------------------------------------------------
#define STAGE_BYTES 98304                  // 3 tiles x 2 subtiles x 16 KB
#define GEMM_SMEM_BYTES (2 * STAGE_BYTES)  // 192 KB
#define NKCHUNK (KDIM / 128)               // 8
#define CPAD 132

template<int MODE>
__global__ __launch_bounds__(512) void mma_gemm_kernel(
    const float* __restrict__ bias, float* __restrict__ C, int N)
{
    extern __shared__ char smem[];
    const __half* Ah = (MODE == 0) ? g_xh : g_ah;
    const __half* Al = (MODE == 0) ? g_xl : g_al;
    const __half* Bm = (MODE == 0) ? g_wq : g_wo;

    const uint32_t sbase = smem_u32(smem);
    const int t = threadIdx.x;
    const int lane = t & 31, wid = t >> 5;
    const int wm = wid & 3, wn = wid >> 2;       // warp grid 4 x 4
    const int brow = blockIdx.y * 128;
    const int bcol = blockIdx.x * 128;

    float acc[2][4][4];
#pragma unroll
    for (int i = 0; i < 2; i++)
#pragma unroll
        for (int j = 0; j < 4; j++)
#pragma unroll
            for (int r = 0; r < 4; r++) acc[i][j][r] = 0.f;

    // Load K-chunk c (k0 = c*128) into stage st.
    // Layout: Ah sub0 @0, Ah sub1 @16K, Al @32K+, B @64K+ (sub stride 16K).
    auto ld_stage = [&](int st, int c) {
        int k0 = c * 128;
        const __half* srcs[3] = { Ah, Al, Bm };
#pragma unroll
        for (int u = 0; u < 12; u++) {
            int cid = u * 512 + t;               // 0..6143
            int t3 = cid >> 11;                  // 0..2
            int w = cid & 2047;
            int row = w >> 4;
            int kc16 = w & 15;
            int sub = kc16 >> 3, kc = kc16 & 7;
            int rowoff = (t3 < 2) ? brow : bcol;
            const void* g = srcs[t3] + (size_t)(rowoff + row) * KDIM
                          + k0 + sub * 64 + kc * 8;
            uint32_t d = sbase + st * STAGE_BYTES + t3 * 32768 + sub * 16384
                       + row * 128 + ((kc ^ (row & 7)) << 4);
            cp_async16(d, g);
        }
    };

    const int arl = lane & 15;
    const int ach = lane >> 4;
    const int brl = (lane & 7) + ((lane >> 4) << 3);
    const int bch = (lane >> 3) & 1;

    auto compute = [&](int st) {
        uint32_t tb = sbase + st * STAGE_BYTES;
        uint32_t ahf[2][2][4], alf[2][2][4], bf[2][4][2];
        auto ldfrag = [&](int u, int buf) {
            int sub = u >> 2;
            int kc0 = 2 * (u & 3);
            uint32_t sb16 = tb + sub * 16384;
#pragma unroll
            for (int i = 0; i < 2; i++) {
                int row = wm * 32 + i * 16 + arl;
                uint32_t off = row * 128 + (((kc0 + ach) ^ (row & 7)) << 4);
                ldmx4(ahf[buf][i], sb16 + off);
                ldmx4(alf[buf][i], sb16 + 32768 + off);
            }
#pragma unroll
            for (int jj = 0; jj < 2; jj++) {
                int row = wn * 32 + jj * 16 + brl;
                uint32_t off = row * 128 + (((kc0 + bch) ^ (row & 7)) << 4);
                uint32_t r[4];
                ldmx4(r, sb16 + 65536 + off);
                bf[buf][2*jj][0] = r[0]; bf[buf][2*jj][1] = r[1];
                bf[buf][2*jj+1][0] = r[2]; bf[buf][2*jj+1][1] = r[3];
            }
        };
        ldfrag(0, 0);
#pragma unroll
        for (int u = 0; u < 8; u++) {
            int cur = u & 1;
            if (u < 7) ldfrag(u + 1, cur ^ 1);
#pragma unroll
            for (int i = 0; i < 2; i++)
#pragma unroll
                for (int j = 0; j < 4; j++) {
                    mma16816(acc[i][j], ahf[cur][i], bf[cur][j]);
                    mma16816(acc[i][j], alf[cur][i], bf[cur][j]);
                }
        }
    };

    ld_stage(0, 0); cp_commit();
    ld_stage(1, 1); cp_commit();
#pragma unroll 1
    for (int c = 0; c < NKCHUNK; c++) {
        if (c == NKCHUNK - 1) cp_wait<0>(); else cp_wait<1>();
        __syncthreads();
        compute(c & 1);
        if (c < NKCHUNK - 2) {
            __syncthreads();                 // all warps done with stage c&1
            ld_stage(c & 1, c + 2);
            cp_commit();
        }
    }

    // ---- staged epilogue: regs -> smem -> coalesced global ----
    __syncthreads();
    float* cs = (float*)smem;             // 128 x CPAD floats
    const int gid = lane >> 2;
    const int tq  = lane & 3;
#pragma unroll
    for (int i = 0; i < 2; i++)
#pragma unroll
        for (int j = 0; j < 4; j++)
#pragma unroll
            for (int r = 0; r < 4; r++) {
                int m = wm * 32 + i * 16 + gid + ((r >> 1) << 3);
                int n = wn * 32 + j * 8 + 2 * tq + (r & 1);
                cs[m * CPAD + n] = acc[i][j][r] + bias[bcol + n];
            }
    __syncthreads();

    {
        int row = t & 127;                // local row
        int q4  = t >> 7;                 // 0..3, 32-float column chunk
        int m = brow + row;
        float vals[32];
#pragma unroll
        for (int u = 0; u < 8; u++)
            *(float4*)&vals[u * 4] = *(float4*)&cs[row * CPAD + q4 * 32 + u * 4];
        if (MODE == 0) {
            int b = m >> 12;
            int l = m & 4095;
            int ng = bcol + q4 * 32;
            int part = ng >> 10;
            int d = ng & 1023;
            int h = d >> 6, e0 = d & 63;
            size_t idx = (((size_t)(b * NHEAD + h)) * SEQ + l) * EDIM + e0;
            float* dst;
            if (part == 0) {
                dst = g_q;
#pragma unroll
                for (int u = 0; u < 32; u++) vals[u] = elu1(vals[u] * 0.125f);
            } else if (part == 1) {
                dst = g_k;
#pragma unroll
                for (int u = 0; u < 32; u++) vals[u] = elu1(vals[u]);
            } else {
                dst = g_v;
            }
#pragma unroll
            for (int u = 0; u < 8; u++)
                *(float4*)&dst[idx + u * 4] = *(float4*)&vals[u * 4];
        } else {
            float* dst = C + (size_t)m * N + bcol + q4 * 32;
#pragma unroll
            for (int u = 0; u < 8; u++)
                *(float4*)&dst[u * 4] = *(float4*)&vals[u * 4];
        }
    }
}

// ---------------------------------------------------------------------------
// Fused K2+K3: per-bh persistent block (512 threads); running KV/ksum prefix
// in registers. Writes the EXCLUSIVE prefix for each chunk.
// ---------------------------------------------------------------------------
__global__ __launch_bounds__(512) void state_scan_kernel() {
    int bh = blockIdx.x;
    __shared__ float Ks[CHUNK * EDIM];
    __shared__ float Vs[CHUNK * EDIM];
    int t = threadIdx.x;
    int e0 = (t >> 4) << 1;      // 2 e-rows per thread (32 groups x 2 = 64)
    int f0 = (t & 15) << 2;      // 4 f-cols

    float run[2][4];
#pragma unroll
    for (int i = 0; i < 2; i++)
#pragma unroll
        for (int x = 0; x < 4; x++) run[i][x] = 0.f;
    float runk = 0.f;

#pragma unroll 1
    for (int c = 0; c < NCHUNK; c++) {
        __syncthreads();
        size_t base = ((size_t)bh * SEQ + (size_t)c * CHUNK) * EDIM;
        for (int s = t; s < CHUNK * EDIM / 4; s += 512) {
            ((float4*)Ks)[s] = *(const float4*)(g_k + base + 4 * s);
            ((float4*)Vs)[s] = *(const float4*)(g_v + base + 4 * s);
        }
        __syncthreads();

        float* kvo = g_kv + ((size_t)bh * NCHUNK + c) * (EDIM * EDIM);
#pragma unroll
        for (int i = 0; i < 2; i++) {
            float4 o = make_float4(run[i][0], run[i][1], run[i][2], run[i][3]);
            *(float4*)&kvo[(e0 + i) * EDIM + f0] = o;
        }
        if (t < EDIM)
            g_ksum[((size_t)bh * NCHUNK + c) * EDIM + t] = runk;

#pragma unroll 4
        for (int j = 0; j < CHUNK; j++) {
            float2 kq = *(float2*)&Ks[j * EDIM + e0];
            float4 vq = *(float4*)&Vs[j * EDIM + f0];
            float kr[2] = {kq.x, kq.y};
            float vr[4] = {vq.x, vq.y, vq.z, vq.w};
#pragma unroll
            for (int i = 0; i < 2; i++)
#pragma unroll
                for (int x = 0; x < 4; x++)
                    run[i][x] = fmaf(kr[i], vr[x], run[i][x]);
        }
        if (t < EDIM) {
            float s = 0.f;
            for (int j = 0; j < CHUNK; j++) s += Ks[j * EDIM + t];
            runk += s;
        }
    }
}

// ---------------------------------------------------------------------------
// K4: per-(bh,chunk) output, 4x4 blocking + float4 loads.
// Writes fp16 hi/lo split directly (feeds the output-projection GEMM).
// ---------------------------------------------------------------------------
#define PAD 68
#define K4_SMEM_FLOATS (5 * 64 * PAD + 64 + 64)
__global__ __launch_bounds__(256) void attn_out_kernel() {
    extern __shared__ float sm[];
    float* Qs   = sm;                  // 64*68
    float* Ks   = Qs + 64 * PAD;
    float* Vs   = Ks + 64 * PAD;
    float* Ss   = Vs + 64 * PAD;
    float* KVs  = Ss + 64 * PAD;
    float* ksum = KVs + 64 * PAD;
    float* denr = ksum + 64;

    int bh = blockIdx.x;
    int c  = blockIdx.y;
    int t  = threadIdx.x;

    size_t base = ((size_t)bh * SEQ + (size_t)c * CHUNK) * EDIM;
    const float* kvp = g_kv + ((size_t)bh * NCHUNK + c) * (EDIM * EDIM);
    for (int s = t; s < CHUNK * EDIM; s += 256) {
        int i = s >> 6, e = s & 63;
        Qs[i * PAD + e] = g_q[base + s];
        Ks[i * PAD + e] = g_k[base + s];
        Vs[i * PAD + e] = g_v[base + s];
        KVs[i * PAD + e] = kvp[s];
    }
    if (t < EDIM) ksum[t] = g_ksum[((size_t)bh * NCHUNK + c) * EDIM + t];
    __syncthreads();

    // pass 1: S = Q K^T, store masked (zeros above diagonal)
    {
        int i0 = (t >> 4) << 2;
        int j0 = (t & 15) << 2;
        float a[4][4];
#pragma unroll
        for (int i = 0; i < 4; i++)
#pragma unroll
            for (int j = 0; j < 4; j++) a[i][j] = 0.f;
#pragma unroll 4
        for (int e = 0; e < EDIM; e += 4) {
            float4 q[4], k[4];
#pragma unroll
            for (int i = 0; i < 4; i++) q[i] = *(float4*)&Qs[(i0 + i) * PAD + e];
#pragma unroll
            for (int j = 0; j < 4; j++) k[j] = *(float4*)&Ks[(j0 + j) * PAD + e];
#pragma unroll
            for (int i = 0; i < 4; i++)
#pragma unroll
                for (int j = 0; j < 4; j++) {
                    a[i][j] = fmaf(q[i].x, k[j].x, a[i][j]);
                    a[i][j] = fmaf(q[i].y, k[j].y, a[i][j]);
                    a[i][j] = fmaf(q[i].z, k[j].z, a[i][j]);
                    a[i][j] = fmaf(q[i].w, k[j].w, a[i][j]);
                }
        }
#pragma unroll
        for (int i = 0; i < 4; i++) {
            float4 o;
            o.x = (j0 + 0 <= i0 + i) ? a[i][0] : 0.f;
            o.y = (j0 + 1 <= i0 + i) ? a[i][1] : 0.f;
            o.z = (j0 + 2 <= i0 + i) ? a[i][2] : 0.f;
            o.w = (j0 + 3 <= i0 + i) ? a[i][3] : 0.f;
            *(float4*)&Ss[(i0 + i) * PAD + j0] = o;
        }
    }
    __syncthreads();

    // denominators
    if (t < CHUNK) {
        int i = t;
        float dr = 0.f, d2 = 0.f;
        for (int j = 0; j < CHUNK; j++) dr += Ss[i * PAD + j];
        for (int e = 0; e < EDIM; e++) d2 = fmaf(Qs[i * PAD + e], ksum[e], d2);
        denr[i] = dr + d2 + EPS_DEN;
    }
    __syncthreads();

    // pass 2: out = (S V + Q KV) / den, write fp16 hi/lo
    {
        int i0 = (t >> 4) << 2;
        int e0 = (t & 15) << 2;
        float a[4][4];
#pragma unroll
        for (int i = 0; i < 4; i++)
#pragma unroll
            for (int x = 0; x < 4; x++) a[i][x] = 0.f;
#pragma unroll 4
        for (int j = 0; j < CHUNK; j += 4) {
            float4 srow[4], vrow[4];
#pragma unroll
            for (int i = 0; i < 4; i++) srow[i] = *(float4*)&Ss[(i0 + i) * PAD + j];
#pragma unroll
            for (int jj = 0; jj < 4; jj++) vrow[jj] = *(float4*)&Vs[(j + jj) * PAD + e0];
#pragma unroll
            for (int i = 0; i < 4; i++) {
                float sv[4] = {srow[i].x, srow[i].y, srow[i].z, srow[i].w};
#pragma unroll
                for (int jj = 0; jj < 4; jj++) {
                    a[i][0] = fmaf(sv[jj], vrow[jj].x, a[i][0]);
                    a[i][1] = fmaf(sv[jj], vrow[jj].y, a[i][1]);
                    a[i][2] = fmaf(sv[jj], vrow[jj].z, a[i][2]);
                    a[i][3] = fmaf(sv[jj], vrow[jj].w, a[i][3]);
                }
            }
        }
#pragma unroll 4
        for (int f = 0; f < EDIM; f += 4) {
            float4 qrow[4], kvr[4];
#pragma unroll
            for (int i = 0; i < 4; i++) qrow[i] = *(float4*)&Qs[(i0 + i) * PAD + f];
#pragma unroll
            for (int jj = 0; jj < 4; jj++) kvr[jj] = *(float4*)&KVs[(f + jj) * PAD + e0];
#pragma unroll
            for (int i = 0; i < 4; i++) {
                float qv[4] = {qrow[i].x, qrow[i].y, qrow[i].z, qrow[i].w};
#pragma unroll
                for (int jj = 0; jj < 4; jj++) {
                    a[i][0] = fmaf(qv[jj], kvr[jj].x, a[i][0]);
                    a[i][1] = fmaf(qv[jj], kvr[jj].y, a[i][1]);
                    a[i][2] = fmaf(qv[jj], kvr[jj].z, a[i][2]);
                    a[i][3] = fmaf(qv[jj], kvr[jj].w, a[i][3]);
                }
            }
        }

        int b = bh >> 4;
        int h = bh & 15;
#pragma unroll
        for (int i = 0; i < 4; i++) {
            int l = c * CHUNK + i0 + i;
            float inv = 1.f / denr[i0 + i];
            size_t idx = ((size_t)b * SEQ + l) * DMODEL + h * EDIM + e0;
            __half hv[4], lv[4];
#pragma unroll
            for (int x = 0; x < 4; x++) {
                float v = a[i][x] * inv;
                hv[x] = __float2half(v);
                lv[x] = __float2half(v - __half2float(hv[x]));
            }
            *(uint2*)(g_ah + idx) = *(uint2*)hv;
            *(uint2*)(g_al + idx) = *(uint2*)lv;
        }
    }
}

// ---------------------------------------------------------------------------
extern "C" void kernel_launch(void* const* d_in, const int* in_sizes, int n_in,
                              void* d_out, int out_size) {
    const float* x     = (const float*)d_in[0];
    const float* W_qkv = (const float*)d_in[1];
    const float* b_qkv = (const float*)d_in[2];
    const float* W_out = (const float*)d_in[3];
    const float* b_out = (const float*)d_in[4];
    float* out = (float*)d_out;

    static int attr_set = 0;
    if (!attr_set) {
        cudaFuncSetAttribute(mma_gemm_kernel<0>,
                             cudaFuncAttributeMaxDynamicSharedMemorySize, GEMM_SMEM_BYTES);
        cudaFuncSetAttribute(mma_gemm_kernel<1>,
                             cudaFuncAttributeMaxDynamicSharedMemorySize, GEMM_SMEM_BYTES);
        cudaFuncSetAttribute(attn_out_kernel,
                             cudaFuncAttributeMaxDynamicSharedMemorySize,
                             K4_SMEM_FLOATS * sizeof(float));
        attr_set = 1;
    }

    // prep
    split_x_kernel<<<(size_t)M_TOK * KDIM / 4 / 256, 256>>>(x);
    transpose_kernel<0><<<dim3(3 * DMODEL / 32, KDIM / 32), dim3(32, 8)>>>(W_qkv);
    transpose_kernel<1><<<dim3(DMODEL / 32, KDIM / 32), dim3(32, 8)>>>(W_out);

    // K1: qkv GEMM
    mma_gemm_kernel<0><<<dim3(3 * DMODEL / 128, M_TOK / 128), 512, GEMM_SMEM_BYTES>>>(
        b_qkv, nullptr, 3 * DMODEL);

    // attention
    state_scan_kernel<<<NBH, 512>>>();
    attn_out_kernel<<<dim3(NBH, NCHUNK), 256, K4_SMEM_FLOATS * sizeof(float)>>>();

    // output projection
    mma_gemm_kernel<1><<<dim3(DMODEL / 128, M_TOK / 128), 512, GEMM_SMEM_BYTES>>>(
        b_out, out, DMODEL);
}

// round 14
// speedup vs baseline: 1.2037x; 1.2019x over previous
#include <cuda_runtime.h>
#include <cuda_fp16.h>
#include <math.h>
#include <stdint.h>

// Problem constants
#define BATCH 4
#define SEQ   4096
#define DMODEL 1024
#define NHEAD 16
#define EDIM  64
#define NBH   (BATCH*NHEAD)       // 64
#define CHUNK 64
#define NCHUNK (SEQ/CHUNK)        // 64
#define M_TOK (BATCH*SEQ)         // 16384
#define KDIM  1024

#define EPS_FEAT 1.0001f
#define EPS_DEN  1e-6f

// ---------------------------------------------------------------------------
// Scratch (device globals, no runtime allocation)
// ---------------------------------------------------------------------------
__device__ float g_q[(size_t)NBH*SEQ*EDIM];
__device__ float g_k[(size_t)NBH*SEQ*EDIM];
__device__ float g_v[(size_t)NBH*SEQ*EDIM];
__device__ float g_kv[(size_t)NBH*NCHUNK*EDIM*EDIM];
__device__ float g_ksum[(size_t)NBH*NCHUNK*EDIM];

// fp16 operands
__device__ __half g_xh[(size_t)M_TOK*KDIM];      // x fp16
__device__ __half g_ah[(size_t)M_TOK*KDIM];      // attn output fp16
__device__ __half g_wq[(size_t)3*DMODEL*KDIM];   // (3072,1024) = W^T fp16
__device__ __half g_wo[(size_t)DMODEL*KDIM];     // (1024,1024) = W^T fp16

__device__ __forceinline__ float elu1(float x) {
    return x > 0.f ? x + EPS_FEAT : expm1f(x) + EPS_FEAT;
}

__device__ __forceinline__ uint32_t smem_u32(const void* p) {
    uint32_t a;
    asm("{ .reg .u64 t; cvta.to.shared.u64 t, %1; cvt.u32.u64 %0, t; }"
        : "=r"(a) : "l"(p));
    return a;
}

__device__ __forceinline__ void cp_async16(uint32_t s, const void* g) {
    asm volatile("cp.async.cg.shared.global [%0], [%1], 16;" :: "r"(s), "l"(g));
}
__device__ __forceinline__ void cp_commit() {
    asm volatile("cp.async.commit_group;");
}
template<int N>
__device__ __forceinline__ void cp_wait() {
    asm volatile("cp.async.wait_group %0;" :: "n"(N));
}

__device__ __forceinline__ void ldmx4(uint32_t* r, uint32_t addr) {
    asm volatile("ldmatrix.sync.aligned.m8n8.x4.shared.b16 {%0,%1,%2,%3}, [%4];"
                 : "=r"(r[0]), "=r"(r[1]), "=r"(r[2]), "=r"(r[3]) : "r"(addr));
}

__device__ __forceinline__ void mma16816(float* d, const uint32_t* a, const uint32_t* b) {
    asm volatile(
        "mma.sync.aligned.m16n8k16.row.col.f32.f16.f16.f32 "
        "{%0,%1,%2,%3}, {%4,%5,%6,%7}, {%8,%9}, {%0,%1,%2,%3};"
        : "+f"(d[0]), "+f"(d[1]), "+f"(d[2]), "+f"(d[3])
        : "r"(a[0]), "r"(a[1]), "r"(a[2]), "r"(a[3]), "r"(b[0]), "r"(b[1]));
}

// ---------------------------------------------------------------------------
// Convert x: fp32 -> fp16
// ---------------------------------------------------------------------------
__global__ __launch_bounds__(256) void split_x_kernel(const float* __restrict__ xin) {
    size_t i = (size_t)blockIdx.x * blockDim.x + threadIdx.x;   // float4 index
    float4 v = ((const float4*)xin)[i];
    __half2* ph = (__half2*)g_xh;
    ph[2*i]   = __half2(__float2half(v.x), __float2half(v.y));
    ph[2*i+1] = __half2(__float2half(v.z), __float2half(v.w));
}

// ---------------------------------------------------------------------------
// Transpose: W (K x N) fp32 -> Wt (N x K) fp16
// ---------------------------------------------------------------------------
template<int WHICH>
__global__ __launch_bounds__(256) void transpose_kernel(const float* __restrict__ W) {
    const int N = (WHICH == 0) ? 3 * DMODEL : DMODEL;
    __half* Th = (WHICH == 0) ? g_wq : g_wo;
    __shared__ float tile[32][33];
    int bx = blockIdx.x * 32;   // n
    int by = blockIdx.y * 32;   // k
    int tx = threadIdx.x, ty = threadIdx.y;
#pragma unroll
    for (int i = 0; i < 32; i += 8)
        tile[ty + i][tx] = W[(size_t)(by + ty + i) * N + bx + tx];
    __syncthreads();
#pragma unroll
    for (int i = 0; i < 32; i += 8) {
        float v = tile[tx][ty + i];
        int n = bx + ty + i, k = by + tx;
        Th[(size_t)n * KDIM + k] = __float2half(v);
    }
}

// ---------------------------------------------------------------------------
// HMMA GEMM (pure fp16): C = A(M,1024) @ Bt(N,1024)^T + bias
// 128x128 CTA tile, 512 threads (16 warps 4x4, 32x32/warp), K-chunk 64,
// 4-stage cp.async (32KB/stage: A, B tiles), fragment double-buffering.
// Staged smem epilogue (CPAD=132 keeps float4 alignment).
// MODE 0: -> q/k/v feature-map scatter ; MODE 1: -> C
// ---------------------------------------------------------------------------
#define STAGE_BYTES 32768
#define GEMM_SMEM_BYTES (4 * STAGE_BYTES)  // 128 KB
#define CPAD 132

template<int MODE>
__global__ __launch_bounds__(512) void mma_gemm_kernel(
    const float* __restrict__ bias, float* __restrict__ C, int N)
{
    extern __shared__ char smem[];
    const __half* Am = (MODE == 0) ? g_xh : g_ah;
    const __half* Bm = (MODE == 0) ? g_wq : g_wo;

    const uint32_t sbase = smem_u32(smem);
    const int t = threadIdx.x;
    const int lane = t & 31, wid = t >> 5;
    const int wm = wid & 3, wn = wid >> 2;       // warp grid 4 x 4
    const int brow = blockIdx.y * 128;
    const int bcol = blockIdx.x * 128;

    float acc[2][4][4];
#pragma unroll
    for (int i = 0; i < 2; i++)
#pragma unroll
        for (int j = 0; j < 4; j++)
#pragma unroll
            for (int r = 0; r < 4; r++) acc[i][j][r] = 0.f;

    auto ld_stage = [&](int st, int c) {
        const __half* srcs[2] = { Am, Bm };
#pragma unroll
        for (int t2 = 0; t2 < 2; t2++) {
            int rowoff = (t2 < 1) ? brow : bcol;
            const __half* src = srcs[t2] + (size_t)rowoff * KDIM + c * 64;
            uint32_t dbase = sbase + st * STAGE_BYTES + t2 * 16384;
#pragma unroll
            for (int u = 0; u < 2; u++) {
                int cid = u * 512 + t;           // 0..1023
                int row = cid >> 3, kc = cid & 7;
                const void* g = src + (size_t)row * KDIM + kc * 8;
                uint32_t d = dbase + row * 128 + ((kc ^ (row & 7)) << 4);
                cp_async16(d, g);
            }
        }
    };

    const int arl = lane & 15;
    const int ach = lane >> 4;
    const int brl = (lane & 7) + ((lane >> 4) << 3);
    const int bch = (lane >> 3) & 1;

    auto compute = [&](int st) {
        uint32_t tb = sbase + st * STAGE_BYTES;
        uint32_t af[2][2][4], bf[2][4][2];
        auto ldfrag = [&](int s, int buf) {
            int kc0 = 2 * s;
#pragma unroll
            for (int i = 0; i < 2; i++) {
                int row = wm * 32 + i * 16 + arl;
                uint32_t off = row * 128 + (((kc0 + ach) ^ (row & 7)) << 4);
                ldmx4(af[buf][i], tb + off);
            }
#pragma unroll
            for (int jj = 0; jj < 2; jj++) {
                int row = wn * 32 + jj * 16 + brl;
                uint32_t off = row * 128 + (((kc0 + bch) ^ (row & 7)) << 4);
                uint32_t r[4];
                ldmx4(r, tb + 16384 + off);
                bf[buf][2*jj][0] = r[0]; bf[buf][2*jj][1] = r[1];
                bf[buf][2*jj+1][0] = r[2]; bf[buf][2*jj+1][1] = r[3];
            }
        };
        ldfrag(0, 0);
#pragma unroll
        for (int s = 0; s < 4; s++) {
            int cur = s & 1;
            if (s < 3) ldfrag(s + 1, cur ^ 1);
#pragma unroll
            for (int i = 0; i < 2; i++)
#pragma unroll
                for (int j = 0; j < 4; j++)
                    mma16816(acc[i][j], af[cur][i], bf[cur][j]);
        }
    };

    ld_stage(0, 0); cp_commit();
    ld_stage(1, 1); cp_commit();
    ld_stage(2, 2); cp_commit();
#pragma unroll 1
    for (int c = 0; c < 16; c++) {
        if (c <= 13) cp_wait<2>();
        else if (c == 14) cp_wait<1>();
        else cp_wait<0>();
        __syncthreads();
        if (c < 13) { ld_stage((c + 3) & 3, c + 3); cp_commit(); }
        compute(c & 3);
    }

    // ---- staged epilogue: regs -> smem -> coalesced global ----
    __syncthreads();
    float* cs = (float*)smem;             // 128 x CPAD floats
    const int gid = lane >> 2;
    const int tq  = lane & 3;
#pragma unroll
    for (int i = 0; i < 2; i++)
#pragma unroll
        for (int j = 0; j < 4; j++)
#pragma unroll
            for (int r = 0; r < 4; r++) {
                int m = wm * 32 + i * 16 + gid + ((r >> 1) << 3);
                int n = wn * 32 + j * 8 + 2 * tq + (r & 1);
                cs[m * CPAD + n] = acc[i][j][r] + bias[bcol + n];
            }
    __syncthreads();

    {
        int row = t & 127;                // local row
        int q4  = t >> 7;                 // 0..3, 32-float column chunk
        int m = brow + row;
        float vals[32];
#pragma unroll
        for (int u = 0; u < 8; u++)
            *(float4*)&vals[u * 4] = *(float4*)&cs[row * CPAD + q4 * 32 + u * 4];
        if (MODE == 0) {
            int b = m >> 12;
            int l = m & 4095;
            int ng = bcol + q4 * 32;
            int part = ng >> 10;
            int d = ng & 1023;
            int h = d >> 6, e0 = d & 63;
            size_t idx = (((size_t)(b * NHEAD + h)) * SEQ + l) * EDIM + e0;
            float* dst;
            if (part == 0) {
                dst = g_q;
#pragma unroll
                for (int u = 0; u < 32; u++) vals[u] = elu1(vals[u] * 0.125f);
            } else if (part == 1) {
                dst = g_k;
#pragma unroll
                for (int u = 0; u < 32; u++) vals[u] = elu1(vals[u]);
            } else {
                dst = g_v;
            }
#pragma unroll
            for (int u = 0; u < 8; u++)
                *(float4*)&dst[idx + u * 4] = *(float4*)&vals[u * 4];
        } else {
            float* dst = C + (size_t)m * N + bcol + q4 * 32;
#pragma unroll
            for (int u = 0; u < 8; u++)
                *(float4*)&dst[u * 4] = *(float4*)&vals[u * 4];
        }
    }
}

// ---------------------------------------------------------------------------
// Fused K2+K3: per-bh persistent block; running KV/ksum prefix in registers.
// Writes the EXCLUSIVE prefix for each chunk (what attn_out consumes).
// ---------------------------------------------------------------------------
__global__ __launch_bounds__(256) void state_scan_kernel() {
    int bh = blockIdx.x;
    __shared__ float Ks[CHUNK * EDIM];
    __shared__ float Vs[CHUNK * EDIM];
    int t = threadIdx.x;
    int e0 = (t >> 4) << 2;
    int f0 = (t & 15) << 2;

    float run[4][4];
#pragma unroll
    for (int i = 0; i < 4; i++)
#pragma unroll
        for (int x = 0; x < 4; x++) run[i][x] = 0.f;
    float runk = 0.f;

#pragma unroll 1
    for (int c = 0; c < NCHUNK; c++) {
        __syncthreads();
        size_t base = ((size_t)bh * SEQ + (size_t)c * CHUNK) * EDIM;
        for (int s = t; s < CHUNK * EDIM / 4; s += 256) {
            ((float4*)Ks)[s] = *(const float4*)(g_k + base + 4 * s);
            ((float4*)Vs)[s] = *(const float4*)(g_v + base + 4 * s);
        }
        __syncthreads();

        float* kvo = g_kv + ((size_t)bh * NCHUNK + c) * (EDIM * EDIM);
#pragma unroll
        for (int i = 0; i < 4; i++) {
            float4 o = make_float4(run[i][0], run[i][1], run[i][2], run[i][3]);
            *(float4*)&kvo[(e0 + i) * EDIM + f0] = o;
        }
        if (t < EDIM)
            g_ksum[((size_t)bh * NCHUNK + c) * EDIM + t] = runk;

#pragma unroll 4
        for (int j = 0; j < CHUNK; j++) {
            float4 kq = *(float4*)&Ks[j * EDIM + e0];
            float4 vq = *(float4*)&Vs[j * EDIM + f0];
            float kr[4] = {kq.x, kq.y, kq.z, kq.w};
            float vr[4] = {vq.x, vq.y, vq.z, vq.w};
#pragma unroll
            for (int i = 0; i < 4; i++)
#pragma unroll
                for (int x = 0; x < 4; x++)
                    run[i][x] = fmaf(kr[i], vr[x], run[i][x]);
        }
        if (t < EDIM) {
            float s = 0.f;
            for (int j = 0; j < CHUNK; j++) s += Ks[j * EDIM + t];
            runk += s;
        }
    }
}

// ---------------------------------------------------------------------------
// K4: per-(bh,chunk) output, 4x4 blocking + float4 loads.
// Writes fp16 directly (feeds the output-projection GEMM).
// ---------------------------------------------------------------------------
#define PAD 68
#define K4_SMEM_FLOATS (5 * 64 * PAD + 64 + 64)
__global__ __launch_bounds__(256) void attn_out_kernel() {
    extern __shared__ float sm[];
    float* Qs   = sm;                  // 64*68
    float* Ks   = Qs + 64 * PAD;
    float* Vs   = Ks + 64 * PAD;
    float* Ss   = Vs + 64 * PAD;
    float* KVs  = Ss + 64 * PAD;
    float* ksum = KVs + 64 * PAD;
    float* denr = ksum + 64;

    int bh = blockIdx.x;
    int c  = blockIdx.y;
    int t  = threadIdx.x;

    size_t base = ((size_t)bh * SEQ + (size_t)c * CHUNK) * EDIM;
    const float* kvp = g_kv + ((size_t)bh * NCHUNK + c) * (EDIM * EDIM);
    for (int s = t; s < CHUNK * EDIM; s += 256) {
        int i = s >> 6, e = s & 63;
        Qs[i * PAD + e] = g_q[base + s];
        Ks[i * PAD + e] = g_k[base + s];
        Vs[i * PAD + e] = g_v[base + s];
        KVs[i * PAD + e] = kvp[s];
    }
    if (t < EDIM) ksum[t] = g_ksum[((size_t)bh * NCHUNK + c) * EDIM + t];
    __syncthreads();

    // pass 1: S = Q K^T, store masked (zeros above diagonal)
    {
        int i0 = (t >> 4) << 2;
        int j0 = (t & 15) << 2;
        float a[4][4];
#pragma unroll
        for (int i = 0; i < 4; i++)
#pragma unroll
            for (int j = 0; j < 4; j++) a[i][j] = 0.f;
#pragma unroll 4
        for (int e = 0; e < EDIM; e += 4) {
            float4 q[4], k[4];
#pragma unroll
            for (int i = 0; i < 4; i++) q[i] = *(float4*)&Qs[(i0 + i) * PAD + e];
#pragma unroll
            for (int j = 0; j < 4; j++) k[j] = *(float4*)&Ks[(j0 + j) * PAD + e];
#pragma unroll
            for (int i = 0; i < 4; i++)
#pragma unroll
                for (int j = 0; j < 4; j++) {
                    a[i][j] = fmaf(q[i].x, k[j].x, a[i][j]);
                    a[i][j] = fmaf(q[i].y, k[j].y, a[i][j]);
                    a[i][j] = fmaf(q[i].z, k[j].z, a[i][j]);
                    a[i][j] = fmaf(q[i].w, k[j].w, a[i][j]);
                }
        }
#pragma unroll
        for (int i = 0; i < 4; i++) {
            float4 o;
            o.x = (j0 + 0 <= i0 + i) ? a[i][0] : 0.f;
            o.y = (j0 + 1 <= i0 + i) ? a[i][1] : 0.f;
            o.z = (j0 + 2 <= i0 + i) ? a[i][2] : 0.f;
            o.w = (j0 + 3 <= i0 + i) ? a[i][3] : 0.f;
            *(float4*)&Ss[(i0 + i) * PAD + j0] = o;
        }
    }
    __syncthreads();

    // denominators
    if (t < CHUNK) {
        int i = t;
        float dr = 0.f, d2 = 0.f;
        for (int j = 0; j < CHUNK; j++) dr += Ss[i * PAD + j];
        for (int e = 0; e < EDIM; e++) d2 = fmaf(Qs[i * PAD + e], ksum[e], d2);
        denr[i] = dr + d2 + EPS_DEN;
    }
    __syncthreads();

    // pass 2: out = (S V + Q KV) / den, write fp16
    {
        int i0 = (t >> 4) << 2;
        int e0 = (t & 15) << 2;
        float a[4][4];
#pragma unroll
        for (int i = 0; i < 4; i++)
#pragma unroll
            for (int x = 0; x < 4; x++) a[i][x] = 0.f;
#pragma unroll 4
        for (int j = 0; j < CHUNK; j += 4) {
            float4 srow[4], vrow[4];
#pragma unroll
            for (int i = 0; i < 4; i++) srow[i] = *(float4*)&Ss[(i0 + i) * PAD + j];
#pragma unroll
            for (int jj = 0; jj < 4; jj++) vrow[jj] = *(float4*)&Vs[(j + jj) * PAD + e0];
#pragma unroll
            for (int i = 0; i < 4; i++) {
                float sv[4] = {srow[i].x, srow[i].y, srow[i].z, srow[i].w};
#pragma unroll
                for (int jj = 0; jj < 4; jj++) {
                    a[i][0] = fmaf(sv[jj], vrow[jj].x, a[i][0]);
                    a[i][1] = fmaf(sv[jj], vrow[jj].y, a[i][1]);
                    a[i][2] = fmaf(sv[jj], vrow[jj].z, a[i][2]);
                    a[i][3] = fmaf(sv[jj], vrow[jj].w, a[i][3]);
                }
            }
        }
#pragma unroll 4
        for (int f = 0; f < EDIM; f += 4) {
            float4 qrow[4], kvr[4];
#pragma unroll
            for (int i = 0; i < 4; i++) qrow[i] = *(float4*)&Qs[(i0 + i) * PAD + f];
#pragma unroll
            for (int jj = 0; jj < 4; jj++) kvr[jj] = *(float4*)&KVs[(f + jj) * PAD + e0];
#pragma unroll
            for (int i = 0; i < 4; i++) {
                float qv[4] = {qrow[i].x, qrow[i].y, qrow[i].z, qrow[i].w};
#pragma unroll
                for (int jj = 0; jj < 4; jj++) {
                    a[i][0] = fmaf(qv[jj], kvr[jj].x, a[i][0]);
                    a[i][1] = fmaf(qv[jj], kvr[jj].y, a[i][1]);
                    a[i][2] = fmaf(qv[jj], kvr[jj].z, a[i][2]);
                    a[i][3] = fmaf(qv[jj], kvr[jj].w, a[i][3]);
                }
            }
        }

        int b = bh >> 4;
        int h = bh & 15;
#pragma unroll
        for (int i = 0; i < 4; i++) {
            int l = c * CHUNK + i0 + i;
            float inv = 1.f / denr[i0 + i];
            size_t idx = ((size_t)b * SEQ + l) * DMODEL + h * EDIM + e0;
            __half hv[4];
#pragma unroll
            for (int x = 0; x < 4; x++)
                hv[x] = __float2half(a[i][x] * inv);
            *(uint2*)(g_ah + idx) = *(uint2*)hv;
        }
    }
}

// ---------------------------------------------------------------------------
extern "C" void kernel_launch(void* const* d_in, const int* in_sizes, int n_in,
                              void* d_out, int out_size) {
    const float* x     = (const float*)d_in[0];
    const float* W_qkv = (const float*)d_in[1];
    const float* b_qkv = (const float*)d_in[2];
    const float* W_out = (const float*)d_in[3];
    const float* b_out = (const float*)d_in[4];
    float* out = (float*)d_out;

    static int attr_set = 0;
    if (!attr_set) {
        cudaFuncSetAttribute(mma_gemm_kernel<0>,
                             cudaFuncAttributeMaxDynamicSharedMemorySize, GEMM_SMEM_BYTES);
        cudaFuncSetAttribute(mma_gemm_kernel<1>,
                             cudaFuncAttributeMaxDynamicSharedMemorySize, GEMM_SMEM_BYTES);
        cudaFuncSetAttribute(attn_out_kernel,
                             cudaFuncAttributeMaxDynamicSharedMemorySize,
                             K4_SMEM_FLOATS * sizeof(float));
        attr_set = 1;
    }

    // prep
    split_x_kernel<<<(size_t)M_TOK * KDIM / 4 / 256, 256>>>(x);
    transpose_kernel<0><<<dim3(3 * DMODEL / 32, KDIM / 32), dim3(32, 8)>>>(W_qkv);
    transpose_kernel<1><<<dim3(DMODEL / 32, KDIM / 32), dim3(32, 8)>>>(W_out);

    // K1: qkv GEMM
    mma_gemm_kernel<0><<<dim3(3 * DMODEL / 128, M_TOK / 128), 512, GEMM_SMEM_BYTES>>>(
        b_qkv, nullptr, 3 * DMODEL);

    // attention
    state_scan_kernel<<<NBH, 256>>>();
    attn_out_kernel<<<dim3(NBH, NCHUNK), 256, K4_SMEM_FLOATS * sizeof(float)>>>();

    // output projection
    mma_gemm_kernel<1><<<dim3(DMODEL / 128, M_TOK / 128), 512, GEMM_SMEM_BYTES>>>(
        b_out, out, DMODEL);
}

// round 16
// speedup vs baseline: 1.3061x; 1.0851x over previous
#include <cuda_runtime.h>
#include <cuda_fp16.h>
#include <math.h>
#include <stdint.h>

// Problem constants
#define BATCH 4
#define SEQ   4096
#define DMODEL 1024
#define NHEAD 16
#define EDIM  64
#define NBH   (BATCH*NHEAD)       // 64
#define CHUNK 64
#define NCHUNK (SEQ/CHUNK)        // 64
#define M_TOK (BATCH*SEQ)         // 16384
#define KDIM  1024

#define EPS_FEAT 1.0001f
#define EPS_DEN  1e-6f

// ---------------------------------------------------------------------------
// Scratch (device globals, no runtime allocation)
// ---------------------------------------------------------------------------
__device__ float g_q[(size_t)NBH*SEQ*EDIM];
__device__ float g_k[(size_t)NBH*SEQ*EDIM];
__device__ float g_v[(size_t)NBH*SEQ*EDIM];
__device__ float g_kv[(size_t)NBH*NCHUNK*EDIM*EDIM];
__device__ float g_ksum[(size_t)NBH*NCHUNK*EDIM];

// fp16 operands
__device__ __half g_xh[(size_t)M_TOK*KDIM];      // x fp16
__device__ __half g_ah[(size_t)M_TOK*KDIM];      // attn output fp16
__device__ __half g_wq[(size_t)3*DMODEL*KDIM];   // (3072,1024) = W^T fp16
__device__ __half g_wo[(size_t)DMODEL*KDIM];     // (1024,1024) = W^T fp16

__device__ __forceinline__ float elu1(float x) {
    return x > 0.f ? x + EPS_FEAT : expm1f(x) + EPS_FEAT;
}

__device__ __forceinline__ uint32_t smem_u32(const void* p) {
    uint32_t a;
    asm("{ .reg .u64 t; cvta.to.shared.u64 t, %1; cvt.u32.u64 %0, t; }"
        : "=r"(a) : "l"(p));
    return a;
}

__device__ __forceinline__ void cp_async16(uint32_t s, const void* g) {
    asm volatile("cp.async.cg.shared.global [%0], [%1], 16;" :: "r"(s), "l"(g));
}
__device__ __forceinline__ void cp_commit() {
    asm volatile("cp.async.commit_group;");
}
template<int N>
__device__ __forceinline__ void cp_wait() {
    asm volatile("cp.async.wait_group %0;" :: "n"(N));
}

__device__ __forceinline__ void ldmx4(uint32_t* r, uint32_t addr) {
    asm volatile("ldmatrix.sync.aligned.m8n8.x4.shared.b16 {%0,%1,%2,%3}, [%4];"
                 : "=r"(r[0]), "=r"(r[1]), "=r"(r[2]), "=r"(r[3]) : "r"(addr));
}

__device__ __forceinline__ void mma16816(float* d, const uint32_t* a, const uint32_t* b) {
    asm volatile(
        "mma.sync.aligned.m16n8k16.row.col.f32.f16.f16.f32 "
        "{%0,%1,%2,%3}, {%4,%5,%6,%7}, {%8,%9}, {%0,%1,%2,%3};"
        : "+f"(d[0]), "+f"(d[1]), "+f"(d[2]), "+f"(d[3])
        : "r"(a[0]), "r"(a[1]), "r"(a[2]), "r"(a[3]), "r"(b[0]), "r"(b[1]));
}

// ---------------------------------------------------------------------------
// Convert x: fp32 -> fp16
// ---------------------------------------------------------------------------
__global__ __launch_bounds__(256) void split_x_kernel(const float* __restrict__ xin) {
    size_t i = (size_t)blockIdx.x * blockDim.x + threadIdx.x;   // float4 index
    float4 v = ((const float4*)xin)[i];
    __half2* ph = (__half2*)g_xh;
    ph[2*i]   = __half2(__float2half(v.x), __float2half(v.y));
    ph[2*i+1] = __half2(__float2half(v.z), __float2half(v.w));
}

// ---------------------------------------------------------------------------
// Transpose: W (K x N) fp32 -> Wt (N x K) fp16
// ---------------------------------------------------------------------------
template<int WHICH>
__global__ __launch_bounds__(256) void transpose_kernel(const float* __restrict__ W) {
    const int N = (WHICH == 0) ? 3 * DMODEL : DMODEL;
    __half* Th = (WHICH == 0) ? g_wq : g_wo;
    __shared__ float tile[32][33];
    int bx = blockIdx.x * 32;   // n
    int by = blockIdx.y * 32;   // k
    int tx = threadIdx.x, ty = threadIdx.y;
#pragma unroll
    for (int i = 0; i < 32; i += 8)
        tile[ty + i][tx] = W[(size_t)(by + ty + i) * N + bx + tx];
    __syncthreads();
#pragma unroll
    for (int i = 0; i < 32; i += 8) {
        float v = tile[tx][ty + i];
        int n = bx + ty + i, k = by + tx;
        Th[(size_t)n * KDIM + k] = __float2half(v);
    }
}

// ---------------------------------------------------------------------------
// HMMA GEMM (pure fp16): C = A(M,1024) @ Bt(N,1024)^T + bias
// 128x128 CTA tile, 512 threads (16 warps 4x4, 32x32/warp), K-chunk 64,
// 3-stage cp.async (32KB/stage) -> 96KB smem -> 2 CTAs/SM.
// Fragment double-buffering; staged smem epilogue (CPAD=132, float4-aligned).
// MODE 0: -> q/k/v feature-map scatter ; MODE 1: -> C
// ---------------------------------------------------------------------------
#define STAGE_BYTES 32768
#define GEMM_SMEM_BYTES (3 * STAGE_BYTES)  // 96 KB
#define CPAD 132

template<int MODE>
__global__ void __launch_bounds__(512, 2) mma_gemm_kernel(
    const float* __restrict__ bias, float* __restrict__ C, int N)
{
    extern __shared__ char smem[];
    const __half* Am = (MODE == 0) ? g_xh : g_ah;
    const __half* Bm = (MODE == 0) ? g_wq : g_wo;

    const uint32_t sbase = smem_u32(smem);
    const int t = threadIdx.x;
    const int lane = t & 31, wid = t >> 5;
    const int wm = wid & 3, wn = wid >> 2;       // warp grid 4 x 4
    const int brow = blockIdx.y * 128;
    const int bcol = blockIdx.x * 128;

    float acc[2][4][4];
#pragma unroll
    for (int i = 0; i < 2; i++)
#pragma unroll
        for (int j = 0; j < 4; j++)
#pragma unroll
            for (int r = 0; r < 4; r++) acc[i][j][r] = 0.f;

    auto ld_stage = [&](int st, int c) {
        const __half* srcs[2] = { Am, Bm };
#pragma unroll
        for (int t2 = 0; t2 < 2; t2++) {
            int rowoff = (t2 < 1) ? brow : bcol;
            const __half* src = srcs[t2] + (size_t)rowoff * KDIM + c * 64;
            uint32_t dbase = sbase + st * STAGE_BYTES + t2 * 16384;
#pragma unroll
            for (int u = 0; u < 2; u++) {
                int cid = u * 512 + t;           // 0..1023
                int row = cid >> 3, kc = cid & 7;
                const void* g = src + (size_t)row * KDIM + kc * 8;
                uint32_t d = dbase + row * 128 + ((kc ^ (row & 7)) << 4);
                cp_async16(d, g);
            }
        }
    };

    const int arl = lane & 15;
    const int ach = lane >> 4;
    const int brl = (lane & 7) + ((lane >> 4) << 3);
    const int bch = (lane >> 3) & 1;

    auto compute = [&](int st) {
        uint32_t tb = sbase + st * STAGE_BYTES;
        uint32_t af[2][2][4], bf[2][4][2];
        auto ldfrag = [&](int s, int buf) {
            int kc0 = 2 * s;
#pragma unroll
            for (int i = 0; i < 2; i++) {
                int row = wm * 32 + i * 16 + arl;
                uint32_t off = row * 128 + (((kc0 + ach) ^ (row & 7)) << 4);
                ldmx4(af[buf][i], tb + off);
            }
#pragma unroll
            for (int jj = 0; jj < 2; jj++) {
                int row = wn * 32 + jj * 16 + brl;
                uint32_t off = row * 128 + (((kc0 + bch) ^ (row & 7)) << 4);
                uint32_t r[4];
                ldmx4(r, tb + 16384 + off);
                bf[buf][2*jj][0] = r[0]; bf[buf][2*jj][1] = r[1];
                bf[buf][2*jj+1][0] = r[2]; bf[buf][2*jj+1][1] = r[3];
            }
        };
        ldfrag(0, 0);
#pragma unroll
        for (int s = 0; s < 4; s++) {
            int cur = s & 1;
            if (s < 3) ldfrag(s + 1, cur ^ 1);
#pragma unroll
            for (int i = 0; i < 2; i++)
#pragma unroll
                for (int j = 0; j < 4; j++)
                    mma16816(acc[i][j], af[cur][i], bf[cur][j]);
        }
    };

    ld_stage(0, 0); cp_commit();
    ld_stage(1, 1); cp_commit();
#pragma unroll 1
    for (int c = 0; c < 16; c++) {
        if (c == 15) cp_wait<0>(); else cp_wait<1>();
        __syncthreads();
        if (c < 14) { ld_stage((c + 2) % 3, c + 2); cp_commit(); }
        compute(c % 3);
    }

    // ---- staged epilogue: regs -> smem -> coalesced global ----
    __syncthreads();
    float* cs = (float*)smem;             // 128 x CPAD floats (~67.6 KB)
    const int gid = lane >> 2;
    const int tq  = lane & 3;
#pragma unroll
    for (int i = 0; i < 2; i++)
#pragma unroll
        for (int j = 0; j < 4; j++)
#pragma unroll
            for (int r = 0; r < 4; r++) {
                int m = wm * 32 + i * 16 + gid + ((r >> 1) << 3);
                int n = wn * 32 + j * 8 + 2 * tq + (r & 1);
                cs[m * CPAD + n] = acc[i][j][r] + bias[bcol + n];
            }
    __syncthreads();

    {
        int row = t & 127;                // local row
        int q4  = t >> 7;                 // 0..3, 32-float column chunk
        int m = brow + row;
        float vals[32];
#pragma unroll
        for (int u = 0; u < 8; u++)
            *(float4*)&vals[u * 4] = *(float4*)&cs[row * CPAD + q4 * 32 + u * 4];
        if (MODE == 0) {
            int b = m >> 12;
            int l = m & 4095;
            int ng = bcol + q4 * 32;
            int part = ng >> 10;
            int d = ng & 1023;
            int h = d >> 6, e0 = d & 63;
            size_t idx = (((size_t)(b * NHEAD + h)) * SEQ + l) * EDIM + e0;
            float* dst;
            if (part == 0) {
                dst = g_q;
#pragma unroll
                for (int u = 0; u < 32; u++) vals[u] = elu1(vals[u] * 0.125f);
            } else if (part == 1) {
                dst = g_k;
#pragma unroll
                for (int u = 0; u < 32; u++) vals[u] = elu1(vals[u]);
            } else {
                dst = g_v;
            }
#pragma unroll
            for (int u = 0; u < 8; u++)
                *(float4*)&dst[idx + u * 4] = *(float4*)&vals[u * 4];
        } else {
            float* dst = C + (size_t)m * N + bcol + q4 * 32;
#pragma unroll
            for (int u = 0; u < 8; u++)
                *(float4*)&dst[u * 4] = *(float4*)&vals[u * 4];
        }
    }
}

// ---------------------------------------------------------------------------
// Fused K2+K3: per-bh persistent block; running KV/ksum prefix in registers.
// Writes the EXCLUSIVE prefix for each chunk (what attn_out consumes).
// ---------------------------------------------------------------------------
__global__ __launch_bounds__(256) void state_scan_kernel() {
    int bh = blockIdx.x;
    __shared__ float Ks[CHUNK * EDIM];
    __shared__ float Vs[CHUNK * EDIM];
    int t = threadIdx.x;
    int e0 = (t >> 4) << 2;
    int f0 = (t & 15) << 2;

    float run[4][4];
#pragma unroll
    for (int i = 0; i < 4; i++)
#pragma unroll
        for (int x = 0; x < 4; x++) run[i][x] = 0.f;
    float runk = 0.f;

#pragma unroll 1
    for (int c = 0; c < NCHUNK; c++) {
        __syncthreads();
        size_t base = ((size_t)bh * SEQ + (size_t)c * CHUNK) * EDIM;
        for (int s = t; s < CHUNK * EDIM / 4; s += 256) {
            ((float4*)Ks)[s] = *(const float4*)(g_k + base + 4 * s);
            ((float4*)Vs)[s] = *(const float4*)(g_v + base + 4 * s);
        }
        __syncthreads();

        float* kvo = g_kv + ((size_t)bh * NCHUNK + c) * (EDIM * EDIM);
#pragma unroll
        for (int i = 0; i < 4; i++) {
            float4 o = make_float4(run[i][0], run[i][1], run[i][2], run[i][3]);
            *(float4*)&kvo[(e0 + i) * EDIM + f0] = o;
        }
        if (t < EDIM)
            g_ksum[((size_t)bh * NCHUNK + c) * EDIM + t] = runk;

#pragma unroll 4
        for (int j = 0; j < CHUNK; j++) {
            float4 kq = *(float4*)&Ks[j * EDIM + e0];
            float4 vq = *(float4*)&Vs[j * EDIM + f0];
            float kr[4] = {kq.x, kq.y, kq.z, kq.w};
            float vr[4] = {vq.x, vq.y, vq.z, vq.w};
#pragma unroll
            for (int i = 0; i < 4; i++)
#pragma unroll
                for (int x = 0; x < 4; x++)
                    run[i][x] = fmaf(kr[i], vr[x], run[i][x]);
        }
        if (t < EDIM) {
            float s = 0.f;
            for (int j = 0; j < CHUNK; j++) s += Ks[j * EDIM + t];
            runk += s;
        }
    }
}

// ---------------------------------------------------------------------------
// K4: per-(bh,chunk) output, 4x4 blocking + float4 loads.
// Writes fp16 directly (feeds the output-projection GEMM).
// ---------------------------------------------------------------------------
#define PAD 68
#define K4_SMEM_FLOATS (5 * 64 * PAD + 64 + 64)
__global__ __launch_bounds__(256) void attn_out_kernel() {
    extern __shared__ float sm[];
    float* Qs   = sm;                  // 64*68
    float* Ks   = Qs + 64 * PAD;
    float* Vs   = Ks + 64 * PAD;
    float* Ss   = Vs + 64 * PAD;
    float* KVs  = Ss + 64 * PAD;
    float* ksum = KVs + 64 * PAD;
    float* denr = ksum + 64;

    int bh = blockIdx.x;
    int c  = blockIdx.y;
    int t  = threadIdx.x;

    size_t base = ((size_t)bh * SEQ + (size_t)c * CHUNK) * EDIM;
    const float* kvp = g_kv + ((size_t)bh * NCHUNK + c) * (EDIM * EDIM);
    for (int s = t; s < CHUNK * EDIM; s += 256) {
        int i = s >> 6, e = s & 63;
        Qs[i * PAD + e] = g_q[base + s];
        Ks[i * PAD + e] = g_k[base + s];
        Vs[i * PAD + e] = g_v[base + s];
        KVs[i * PAD + e] = kvp[s];
    }
    if (t < EDIM) ksum[t] = g_ksum[((size_t)bh * NCHUNK + c) * EDIM + t];
    __syncthreads();

    // pass 1: S = Q K^T, store masked (zeros above diagonal)
    {
        int i0 = (t >> 4) << 2;
        int j0 = (t & 15) << 2;
        float a[4][4];
#pragma unroll
        for (int i = 0; i < 4; i++)
#pragma unroll
            for (int j = 0; j < 4; j++) a[i][j] = 0.f;
#pragma unroll 4
        for (int e = 0; e < EDIM; e += 4) {
            float4 q[4], k[4];
#pragma unroll
            for (int i = 0; i < 4; i++) q[i] = *(float4*)&Qs[(i0 + i) * PAD + e];
#pragma unroll
            for (int j = 0; j < 4; j++) k[j] = *(float4*)&Ks[(j0 + j) * PAD + e];
#pragma unroll
            for (int i = 0; i < 4; i++)
#pragma unroll
                for (int j = 0; j < 4; j++) {
                    a[i][j] = fmaf(q[i].x, k[j].x, a[i][j]);
                    a[i][j] = fmaf(q[i].y, k[j].y, a[i][j]);
                    a[i][j] = fmaf(q[i].z, k[j].z, a[i][j]);
                    a[i][j] = fmaf(q[i].w, k[j].w, a[i][j]);
                }
        }
#pragma unroll
        for (int i = 0; i < 4; i++) {
            float4 o;
            o.x = (j0 + 0 <= i0 + i) ? a[i][0] : 0.f;
            o.y = (j0 + 1 <= i0 + i) ? a[i][1] : 0.f;
            o.z = (j0 + 2 <= i0 + i) ? a[i][2] : 0.f;
            o.w = (j0 + 3 <= i0 + i) ? a[i][3] : 0.f;
            *(float4*)&Ss[(i0 + i) * PAD + j0] = o;
        }
    }
    __syncthreads();

    // denominators
    if (t < CHUNK) {
        int i = t;
        float dr = 0.f, d2 = 0.f;
        for (int j = 0; j < CHUNK; j++) dr += Ss[i * PAD + j];
        for (int e = 0; e < EDIM; e++) d2 = fmaf(Qs[i * PAD + e], ksum[e], d2);
        denr[i] = dr + d2 + EPS_DEN;
    }
    __syncthreads();

    // pass 2: out = (S V + Q KV) / den, write fp16
    {
        int i0 = (t >> 4) << 2;
        int e0 = (t & 15) << 2;
        float a[4][4];
#pragma unroll
        for (int i = 0; i < 4; i++)
#pragma unroll
            for (int x = 0; x < 4; x++) a[i][x] = 0.f;
#pragma unroll 4
        for (int j = 0; j < CHUNK; j += 4) {
            float4 srow[4], vrow[4];
#pragma unroll
            for (int i = 0; i < 4; i++) srow[i] = *(float4*)&Ss[(i0 + i) * PAD + j];
#pragma unroll
            for (int jj = 0; jj < 4; jj++) vrow[jj] = *(float4*)&Vs[(j + jj) * PAD + e0];
#pragma unroll
            for (int i = 0; i < 4; i++) {
                float sv[4] = {srow[i].x, srow[i].y, srow[i].z, srow[i].w};
#pragma unroll
                for (int jj = 0; jj < 4; jj++) {
                    a[i][0] = fmaf(sv[jj], vrow[jj].x, a[i][0]);
                    a[i][1] = fmaf(sv[jj], vrow[jj].y, a[i][1]);
                    a[i][2] = fmaf(sv[jj], vrow[jj].z, a[i][2]);
                    a[i][3] = fmaf(sv[jj], vrow[jj].w, a[i][3]);
                }
            }
        }
#pragma unroll 4
        for (int f = 0; f < EDIM; f += 4) {
            float4 qrow[4], kvr[4];
#pragma unroll
            for (int i = 0; i < 4; i++) qrow[i] = *(float4*)&Qs[(i0 + i) * PAD + f];
#pragma unroll
            for (int jj = 0; jj < 4; jj++) kvr[jj] = *(float4*)&KVs[(f + jj) * PAD + e0];
#pragma unroll
            for (int i = 0; i < 4; i++) {
                float qv[4] = {qrow[i].x, qrow[i].y, qrow[i].z, qrow[i].w};
#pragma unroll
                for (int jj = 0; jj < 4; jj++) {
                    a[i][0] = fmaf(qv[jj], kvr[jj].x, a[i][0]);
                    a[i][1] = fmaf(qv[jj], kvr[jj].y, a[i][1]);
                    a[i][2] = fmaf(qv[jj], kvr[jj].z, a[i][2]);
                    a[i][3] = fmaf(qv[jj], kvr[jj].w, a[i][3]);
                }
            }
        }

        int b = bh >> 4;
        int h = bh & 15;
#pragma unroll
        for (int i = 0; i < 4; i++) {
            int l = c * CHUNK + i0 + i;
            float inv = 1.f / denr[i0 + i];
            size_t idx = ((size_t)b * SEQ + l) * DMODEL + h * EDIM + e0;
            __half hv[4];
#pragma unroll
            for (int x = 0; x < 4; x++)
                hv[x] = __float2half(a[i][x] * inv);
            *(uint2*)(g_ah + idx) = *(uint2*)hv;
        }
    }
}

// ---------------------------------------------------------------------------
extern "C" void kernel_launch(void* const* d_in, const int* in_sizes, int n_in,
                              void* d_out, int out_size) {
    const float* x     = (const float*)d_in[0];
    const float* W_qkv = (const float*)d_in[1];
    const float* b_qkv = (const float*)d_in[2];
    const float* W_out = (const float*)d_in[3];
    const float* b_out = (const float*)d_in[4];
    float* out = (float*)d_out;

    static int attr_set = 0;
    if (!attr_set) {
        cudaFuncSetAttribute(mma_gemm_kernel<0>,
                             cudaFuncAttributeMaxDynamicSharedMemorySize, GEMM_SMEM_BYTES);
        cudaFuncSetAttribute(mma_gemm_kernel<1>,
                             cudaFuncAttributeMaxDynamicSharedMemorySize, GEMM_SMEM_BYTES);
        cudaFuncSetAttribute(attn_out_kernel,
                             cudaFuncAttributeMaxDynamicSharedMemorySize,
                             K4_SMEM_FLOATS * sizeof(float));
        attr_set = 1;
    }

    // prep
    split_x_kernel<<<(size_t)M_TOK * KDIM / 4 / 256, 256>>>(x);
    transpose_kernel<0><<<dim3(3 * DMODEL / 32, KDIM / 32), dim3(32, 8)>>>(W_qkv);
    transpose_kernel<1><<<dim3(DMODEL / 32, KDIM / 32), dim3(32, 8)>>>(W_out);

    // K1: qkv GEMM
    mma_gemm_kernel<0><<<dim3(3 * DMODEL / 128, M_TOK / 128), 512, GEMM_SMEM_BYTES>>>(
        b_qkv, nullptr, 3 * DMODEL);

    // attention
    state_scan_kernel<<<NBH, 256>>>();
    attn_out_kernel<<<dim3(NBH, NCHUNK), 256, K4_SMEM_FLOATS * sizeof(float)>>>();

    // output projection
    mma_gemm_kernel<1><<<dim3(DMODEL / 128, M_TOK / 128), 512, GEMM_SMEM_BYTES>>>(
        b_out, out, DMODEL);
}